// round 14
// baseline (speedup 1.0000x reference)
#include <cuda_runtime.h>

#define LN_EPS 1e-5f

// 8 lanes per row, 4 rows per warp, 32 warps per block => 128 rows/block.
// Identical per-warp memory geometry to the 291us best (4x LDG.128/thread,
// 4 full 128B lines per warp load instruction, streaming hints on x/out);
// 1024-thread blocks halve block-dispatch count again (grid 15625).
__global__ void __launch_bounds__(1024) typenorm_kernel(
    const int*    __restrict__ types,   // type_list (int32 view)
    const float4* __restrict__ x,       // [N, 32] float4 view of [N,128] f32
    const float4* __restrict__ gamma,   // [T, 32]
    const float4* __restrict__ beta,    // [T, 32]
    float4*       __restrict__ out,     // [N, 32]
    int n_rows)
{
    const int warp = threadIdx.x >> 5;
    const int lane = threadIdx.x & 31;
    const int sub  = lane & 7;          // position within row (8 lanes/row)
    const int r    = lane >> 3;         // which of the warp's 4 rows

    const int row = (blockIdx.x << 7) + (warp << 2) + r;
    if (row >= n_rows) return;

    const float4* xr = x + row * 32;

    // Front-batched independent streaming loads: MLP=4 per thread.
    float4 v0 = __ldcs(&xr[sub +  0]);
    float4 v1 = __ldcs(&xr[sub +  8]);
    float4 v2 = __ldcs(&xr[sub + 16]);
    float4 v3 = __ldcs(&xr[sub + 24]);

    // Local accumulation over 16 elements.
    float s  = ((v0.x + v0.y) + (v0.z + v0.w)) + ((v1.x + v1.y) + (v1.z + v1.w))
             + ((v2.x + v2.y) + (v2.z + v2.w)) + ((v3.x + v3.y) + (v3.z + v3.w));
    float ss = v0.x*v0.x + v0.y*v0.y + v0.z*v0.z + v0.w*v0.w
             + v1.x*v1.x + v1.y*v1.y + v1.z*v1.z + v1.w*v1.w
             + v2.x*v2.x + v2.y*v2.y + v2.z*v2.z + v2.w*v2.w
             + v3.x*v3.x + v3.y*v3.y + v3.z*v3.z + v3.w*v3.w;

    // Cross-lane reduction within aligned 8-lane group: 3 steps.
    #pragma unroll
    for (int off = 4; off > 0; off >>= 1) {
        s  += __shfl_xor_sync(0xFFFFFFFFu, s,  off);
        ss += __shfl_xor_sync(0xFFFFFFFFu, ss, off);
    }

    const float inv_d = 1.0f / 128.0f;
    const float mean  = s * inv_d;
    const float var   = fmaf(ss, inv_d, -mean * mean);  // biased variance
    const float rstd  = rsqrtf(var + LN_EPS);

    // Type-indexed affine params: 4 KB tables, L1/L2 resident.
    const int t = __ldg(&types[row]);
    const float4* gr = gamma + t * 32;
    const float4* br = beta  + t * 32;

    float4 g0 = __ldg(&gr[sub +  0]);
    float4 g1 = __ldg(&gr[sub +  8]);
    float4 g2 = __ldg(&gr[sub + 16]);
    float4 g3 = __ldg(&gr[sub + 24]);
    float4 b0 = __ldg(&br[sub +  0]);
    float4 b1 = __ldg(&br[sub +  8]);
    float4 b2 = __ldg(&br[sub + 16]);
    float4 b3 = __ldg(&br[sub + 24]);

    float4* outr = out + row * 32;
    float4 o;

    o.x = fmaf((v0.x - mean) * rstd, g0.x, b0.x);
    o.y = fmaf((v0.y - mean) * rstd, g0.y, b0.y);
    o.z = fmaf((v0.z - mean) * rstd, g0.z, b0.z);
    o.w = fmaf((v0.w - mean) * rstd, g0.w, b0.w);
    __stcs(&outr[sub + 0], o);

    o.x = fmaf((v1.x - mean) * rstd, g1.x, b1.x);
    o.y = fmaf((v1.y - mean) * rstd, g1.y, b1.y);
    o.z = fmaf((v1.z - mean) * rstd, g1.z, b1.z);
    o.w = fmaf((v1.w - mean) * rstd, g1.w, b1.w);
    __stcs(&outr[sub + 8], o);

    o.x = fmaf((v2.x - mean) * rstd, g2.x, b2.x);
    o.y = fmaf((v2.y - mean) * rstd, g2.y, b2.y);
    o.z = fmaf((v2.z - mean) * rstd, g2.z, b2.z);
    o.w = fmaf((v2.w - mean) * rstd, g2.w, b2.w);
    __stcs(&outr[sub + 16], o);

    o.x = fmaf((v3.x - mean) * rstd, g3.x, b3.x);
    o.y = fmaf((v3.y - mean) * rstd, g3.y, b3.y);
    o.z = fmaf((v3.z - mean) * rstd, g3.z, b3.z);
    o.w = fmaf((v3.w - mean) * rstd, g3.w, b3.w);
    __stcs(&outr[sub + 24], o);
}

extern "C" void kernel_launch(void* const* d_in, const int* in_sizes, int n_in,
                              void* d_out, int out_size)
{
    const int*    types = (const int*)   d_in[0];
    const float4* x     = (const float4*)d_in[1];
    const float4* gamma = (const float4*)d_in[2];
    const float4* beta  = (const float4*)d_in[3];
    float4*       out   = (float4*)      d_out;

    const int n_rows = in_sizes[1] / 128;

    const int rows_per_block = 128;
    const int blocks = (n_rows + rows_per_block - 1) / rows_per_block;
    typenorm_kernel<<<blocks, 1024>>>(types, x, gamma, beta, out, n_rows);
}

// round 16
// speedup vs baseline: 1.0206x; 1.0206x over previous
#include <cuda_runtime.h>

#define LN_EPS 1e-5f

// FINAL — best measured configuration (291.1 us, ~6.94 TB/s of ~7.0 achievable):
// 8 lanes per row, 4 rows per warp, 16 warps per block => 64 rows/block.
// Each thread front-batches 4x LDG.128 (MLP=4); each warp-level load
// instruction covers exactly 4 full 128B cache lines. Streaming hints on
// the 2 GB single-touch x/out traffic; gamma/beta/types stay L1-resident.
// 512-thread blocks: dispatch-amortization sweet spot (256 and 1024 both
// measured slower).
__global__ void __launch_bounds__(512) typenorm_kernel(
    const int*    __restrict__ types,   // type_list (int32 view)
    const float4* __restrict__ x,       // [N, 32] float4 view of [N,128] f32
    const float4* __restrict__ gamma,   // [T, 32]
    const float4* __restrict__ beta,    // [T, 32]
    float4*       __restrict__ out,     // [N, 32]
    int n_rows)
{
    const int warp = threadIdx.x >> 5;
    const int lane = threadIdx.x & 31;
    const int sub  = lane & 7;          // position within row (8 lanes/row)
    const int r    = lane >> 3;         // which of the warp's 4 rows

    const int row = (blockIdx.x << 6) + (warp << 2) + r;
    if (row >= n_rows) return;

    const float4* xr = x + row * 32;

    // Front-batched independent streaming loads: MLP=4 per thread.
    float4 v0 = __ldcs(&xr[sub +  0]);
    float4 v1 = __ldcs(&xr[sub +  8]);
    float4 v2 = __ldcs(&xr[sub + 16]);
    float4 v3 = __ldcs(&xr[sub + 24]);

    // Local accumulation over 16 elements.
    float s  = ((v0.x + v0.y) + (v0.z + v0.w)) + ((v1.x + v1.y) + (v1.z + v1.w))
             + ((v2.x + v2.y) + (v2.z + v2.w)) + ((v3.x + v3.y) + (v3.z + v3.w));
    float ss = v0.x*v0.x + v0.y*v0.y + v0.z*v0.z + v0.w*v0.w
             + v1.x*v1.x + v1.y*v1.y + v1.z*v1.z + v1.w*v1.w
             + v2.x*v2.x + v2.y*v2.y + v2.z*v2.z + v2.w*v2.w
             + v3.x*v3.x + v3.y*v3.y + v3.z*v3.z + v3.w*v3.w;

    // Cross-lane reduction within aligned 8-lane group: 3 steps.
    #pragma unroll
    for (int off = 4; off > 0; off >>= 1) {
        s  += __shfl_xor_sync(0xFFFFFFFFu, s,  off);
        ss += __shfl_xor_sync(0xFFFFFFFFu, ss, off);
    }

    const float inv_d = 1.0f / 128.0f;
    const float mean  = s * inv_d;
    const float var   = fmaf(ss, inv_d, -mean * mean);  // biased variance
    const float rstd  = rsqrtf(var + LN_EPS);

    // Type-indexed affine params: 4 KB tables, L1/L2 resident.
    const int t = __ldg(&types[row]);
    const float4* gr = gamma + t * 32;
    const float4* br = beta  + t * 32;

    float4 g0 = __ldg(&gr[sub +  0]);
    float4 g1 = __ldg(&gr[sub +  8]);
    float4 g2 = __ldg(&gr[sub + 16]);
    float4 g3 = __ldg(&gr[sub + 24]);
    float4 b0 = __ldg(&br[sub +  0]);
    float4 b1 = __ldg(&br[sub +  8]);
    float4 b2 = __ldg(&br[sub + 16]);
    float4 b3 = __ldg(&br[sub + 24]);

    float4* outr = out + row * 32;
    float4 o;

    o.x = fmaf((v0.x - mean) * rstd, g0.x, b0.x);
    o.y = fmaf((v0.y - mean) * rstd, g0.y, b0.y);
    o.z = fmaf((v0.z - mean) * rstd, g0.z, b0.z);
    o.w = fmaf((v0.w - mean) * rstd, g0.w, b0.w);
    __stcs(&outr[sub + 0], o);

    o.x = fmaf((v1.x - mean) * rstd, g1.x, b1.x);
    o.y = fmaf((v1.y - mean) * rstd, g1.y, b1.y);
    o.z = fmaf((v1.z - mean) * rstd, g1.z, b1.z);
    o.w = fmaf((v1.w - mean) * rstd, g1.w, b1.w);
    __stcs(&outr[sub + 8], o);

    o.x = fmaf((v2.x - mean) * rstd, g2.x, b2.x);
    o.y = fmaf((v2.y - mean) * rstd, g2.y, b2.y);
    o.z = fmaf((v2.z - mean) * rstd, g2.z, b2.z);
    o.w = fmaf((v2.w - mean) * rstd, g2.w, b2.w);
    __stcs(&outr[sub + 16], o);

    o.x = fmaf((v3.x - mean) * rstd, g3.x, b3.x);
    o.y = fmaf((v3.y - mean) * rstd, g3.y, b3.y);
    o.z = fmaf((v3.z - mean) * rstd, g3.z, b3.z);
    o.w = fmaf((v3.w - mean) * rstd, g3.w, b3.w);
    __stcs(&outr[sub + 24], o);
}

extern "C" void kernel_launch(void* const* d_in, const int* in_sizes, int n_in,
                              void* d_out, int out_size)
{
    const int*    types = (const int*)   d_in[0];
    const float4* x     = (const float4*)d_in[1];
    const float4* gamma = (const float4*)d_in[2];
    const float4* beta  = (const float4*)d_in[3];
    float4*       out   = (float4*)      d_out;

    const int n_rows = in_sizes[1] / 128;

    const int rows_per_block = 64;
    const int blocks = (n_rows + rows_per_block - 1) / rows_per_block;
    typenorm_kernel<<<blocks, 512>>>(types, x, gamma, beta, out, n_rows);
}